// round 14
// baseline (speedup 1.0000x reference)
#include <cuda_runtime.h>
#include <cuda_bf16.h>
#include <cstdint>
#include <cstddef>

#define BATCH 32
#define C_IN  256
#define NPIX  1024
#define D8    32
#define KT    64
#define NTILES 16
#define MROWS 128

// Scratch (device globals: allocation-free)
__device__ float g_qt[BATCH * NPIX * D8];            // [b][n][32]  q (tf32)
__device__ float g_kt[BATCH * NPIX * D8];            // [b][n][32]  k (tf32)
__device__ __nv_bfloat16 g_v[BATCH * C_IN * NPIX];   // [b][c][n]   v (bf16)

// ---------------------------------------------------------------------------
// helpers
// ---------------------------------------------------------------------------
__device__ __forceinline__ float to_tf32(float f) {
    uint32_t u;
    asm("cvt.rna.tf32.f32 %0, %1;" : "=r"(u) : "f"(f));
    return __uint_as_float(u);
}
__device__ __forceinline__ uint32_t bf2(float lo, float hi) {
    uint32_t r;
    asm("cvt.rn.bf16x2.f32 %0, %1, %2;" : "=r"(r) : "f"(hi), "f"(lo));
    return r;
}
__device__ __forceinline__ uint32_t smem_u32(const void* p) {
    uint32_t a;
    asm("{ .reg .u64 t; cvta.to.shared.u64 t, %1; cvt.u32.u64 %0, t; }"
        : "=r"(a) : "l"(p));
    return a;
}
__device__ __forceinline__ void mma16n8k8(float* d, const float* a, const float* b) {
    asm volatile("mma.sync.aligned.m16n8k8.row.col.f32.tf32.tf32.f32 "
        "{%0,%1,%2,%3}, {%4,%5,%6,%7}, {%8,%9}, {%0,%1,%2,%3};"
        : "+f"(d[0]), "+f"(d[1]), "+f"(d[2]), "+f"(d[3])
        : "r"(__float_as_uint(a[0])), "r"(__float_as_uint(a[1])),
          "r"(__float_as_uint(a[2])), "r"(__float_as_uint(a[3])),
          "r"(__float_as_uint(b[0])), "r"(__float_as_uint(b[1])));
}
__device__ __forceinline__ void mma_bf16(float* d, const uint32_t* a,
                                         uint32_t b0, uint32_t b1) {
    asm volatile("mma.sync.aligned.m16n8k16.row.col.f32.bf16.bf16.f32 "
        "{%0,%1,%2,%3}, {%4,%5,%6,%7}, {%8,%9}, {%0,%1,%2,%3};"
        : "+f"(d[0]), "+f"(d[1]), "+f"(d[2]), "+f"(d[3])
        : "r"(a[0]), "r"(a[1]), "r"(a[2]), "r"(a[3]), "r"(b0), "r"(b1));
}
__device__ __forceinline__ void cp16(uint32_t dst, const void* src) {
    asm volatile("cp.async.cg.shared.global [%0], [%1], 16;" :: "r"(dst), "l"(src));
}
#define CP_COMMIT() asm volatile("cp.async.commit_group;" ::: "memory")
#define CP_WAIT1()  asm volatile("cp.async.wait_group 1;" ::: "memory")
#define CP_WAIT0()  asm volatile("cp.async.wait_group 0;" ::: "memory")

// ---------------------------------------------------------------------------
// FUSED projection kernel: q, k, v in one pass over x.
// A = x^T tile [128 px][k], B = concat(Wq, Wk, Wv) [320 ch][k].
// 512 threads = 16 warps: 4 px-groups (32 rows) x 4 ch-groups (80 ch).
// x tile: xs[32 k][136 pad]; W tile: ws[320 ch][36 pad] — conflict-free.
// Epilogue: ch<32 -> q [b][n][32] tf32, ch<64 -> k, else v -> bf16 SMEM
// transpose then coalesced [b][c][n] stores.
// ---------------------------------------------------------------------------
constexpr int PX_STRIDE = 136;
constexpr int PX_BUF    = 32 * PX_STRIDE;            // 4352 floats
constexpr int F_WS      = 2 * PX_BUF;                // 8704
constexpr int F_WBUF    = 320 * 36;                  // 11520
constexpr int F_SMEM    = (2 * PX_BUF + 2 * F_WBUF) * 4;   // 126976 B

__global__ void __launch_bounds__(512, 1) proj_fused(
    const float* __restrict__ x,
    const float* __restrict__ Wq, const float* __restrict__ bq,
    const float* __restrict__ Wk, const float* __restrict__ bk,
    const float* __restrict__ Wv, const float* __restrict__ bv)
{
    extern __shared__ float sm[];
    const int tid = threadIdx.x, lane = tid & 31, wid = tid >> 5;
    const int b = blockIdx.z, n0 = blockIdx.x * 128;
    const int m0  = (wid >> 2) * 32;     // 32-px slab
    const int ch0 = (wid & 3) * 80;      // 80-ch slab
    const int g = lane >> 2, t = lane & 3;
    const uint32_t sb = smem_u32(sm);
    const float* xb = x + (size_t)b * C_IN * NPIX;

    #pragma unroll
    for (int pb = 0; pb < 2; pb++) {
        const int kt = pb * 32;
        #pragma unroll
        for (int i = tid; i < 1024; i += 512) {
            int r = i >> 5, cg = i & 31;
            cp16(sb + (uint32_t)(pb * PX_BUF + r * PX_STRIDE + cg * 4) * 4,
                 xb + (size_t)(kt + r) * NPIX + n0 + cg * 4);
        }
        #pragma unroll
        for (int i = tid; i < 2560; i += 512) {
            int r = i >> 3, cg = i & 7;
            const float* src = (r < 32)  ? Wq + (size_t)r * C_IN + kt + cg * 4
                             : (r < 64)  ? Wk + (size_t)(r - 32) * C_IN + kt + cg * 4
                                         : Wv + (size_t)(r - 64) * C_IN + kt + cg * 4;
            cp16(sb + (uint32_t)(F_WS + pb * F_WBUF + r * 36 + cg * 4) * 4, src);
        }
        CP_COMMIT();
    }

    float acc[2][10][4] = {};

    #pragma unroll 1
    for (int j = 0; j < 8; j++) {
        if (j < 7) { CP_WAIT1(); } else { CP_WAIT0(); }
        __syncthreads();
        const int buf = j & 1;
        const float* xs = sm + buf * PX_BUF;
        const float* ws = sm + F_WS + buf * F_WBUF + ch0 * 36;

        #pragma unroll
        for (int k8 = 0; k8 < 4; k8++) {
            const int k = k8 * 8 + t;
            float a0[4], a1[4];
            a0[0] = xs[k * PX_STRIDE + m0 + g];
            a0[1] = xs[k * PX_STRIDE + m0 + g + 8];
            a0[2] = xs[(k + 4) * PX_STRIDE + m0 + g];
            a0[3] = xs[(k + 4) * PX_STRIDE + m0 + g + 8];
            a1[0] = xs[k * PX_STRIDE + m0 + g + 16];
            a1[1] = xs[k * PX_STRIDE + m0 + g + 24];
            a1[2] = xs[(k + 4) * PX_STRIDE + m0 + g + 16];
            a1[3] = xs[(k + 4) * PX_STRIDE + m0 + g + 24];
            #pragma unroll
            for (int n8 = 0; n8 < 10; n8++) {
                float bb[2];
                bb[0] = ws[(n8 * 8 + g) * 36 + k];
                bb[1] = ws[(n8 * 8 + g) * 36 + k + 4];
                mma16n8k8(acc[0][n8], a0, bb);
                mma16n8k8(acc[1][n8], a1, bb);
            }
        }
        __syncthreads();

        if (j + 2 < 8) {
            const int kt = (j + 2) * 32;
            #pragma unroll
            for (int i = tid; i < 1024; i += 512) {
                int r = i >> 5, cg = i & 31;
                cp16(sb + (uint32_t)(buf * PX_BUF + r * PX_STRIDE + cg * 4) * 4,
                     xb + (size_t)(kt + r) * NPIX + n0 + cg * 4);
            }
            #pragma unroll
            for (int i = tid; i < 2560; i += 512) {
                int r = i >> 3, cg = i & 7;
                const float* src = (r < 32)  ? Wq + (size_t)r * C_IN + kt + cg * 4
                                 : (r < 64)  ? Wk + (size_t)(r - 32) * C_IN + kt + cg * 4
                                             : Wv + (size_t)(r - 64) * C_IN + kt + cg * 4;
                cp16(sb + (uint32_t)(F_WS + buf * F_WBUF + r * 36 + cg * 4) * 4, src);
            }
            CP_COMMIT();
        }
    }

    // ---- epilogue: scatter q / k, transpose v ----
    __nv_bfloat16* Ts = (__nv_bfloat16*)sm;   // [256 vch][136 px], reuses buffers
    #pragma unroll
    for (int mt2 = 0; mt2 < 2; mt2++) {
        const int row = m0 + mt2 * 16 + g;    // local pixel 0..127
        #pragma unroll
        for (int n8 = 0; n8 < 10; n8++) {
            const int ch = ch0 + n8 * 8 + 2 * t;
            if (ch < 32) {               // ---- q ----
                float b0 = bq[ch], b1 = bq[ch + 1];
                float2 lo = make_float2(to_tf32(acc[mt2][n8][0] + b0),
                                        to_tf32(acc[mt2][n8][1] + b1));
                float2 hi = make_float2(to_tf32(acc[mt2][n8][2] + b0),
                                        to_tf32(acc[mt2][n8][3] + b1));
                *(float2*)&g_qt[((size_t)b * NPIX + n0 + row) * D8 + ch] = lo;
                *(float2*)&g_qt[((size_t)b * NPIX + n0 + row + 8) * D8 + ch] = hi;
            } else if (ch < 64) {        // ---- k ----
                const int col = ch - 32;
                float b0 = bk[col], b1 = bk[col + 1];
                float2 lo = make_float2(to_tf32(acc[mt2][n8][0] + b0),
                                        to_tf32(acc[mt2][n8][1] + b1));
                float2 hi = make_float2(to_tf32(acc[mt2][n8][2] + b0),
                                        to_tf32(acc[mt2][n8][3] + b1));
                *(float2*)&g_kt[((size_t)b * NPIX + n0 + row) * D8 + col] = lo;
                *(float2*)&g_kt[((size_t)b * NPIX + n0 + row + 8) * D8 + col] = hi;
            } else {                     // ---- v -> SMEM transpose ----
                const int vc = ch - 64;
                float b0 = bv[vc], b1 = bv[vc + 1];
                Ts[vc * 136 + row]           = __float2bfloat16(acc[mt2][n8][0] + b0);
                Ts[(vc + 1) * 136 + row]     = __float2bfloat16(acc[mt2][n8][1] + b1);
                Ts[vc * 136 + row + 8]       = __float2bfloat16(acc[mt2][n8][2] + b0);
                Ts[(vc + 1) * 136 + row + 8] = __float2bfloat16(acc[mt2][n8][3] + b1);
            }
        }
    }
    __syncthreads();
    #pragma unroll
    for (int i = tid; i < 256 * 64; i += 512) {
        int c = i >> 6, w = i & 63;
        ((uint32_t*)&g_v[((size_t)b * C_IN + c) * NPIX + n0])[w] =
            ((const uint32_t*)&Ts[c * 136])[w];
    }
}

// ---------------------------------------------------------------------------
// Flash attention: QK tf32 mma, AV bf16 mma.  MROWS = 128 (R13 config).
// Warp wid owns query rows [wid*16, wid*16+16) and ALL 256 channels.
// P handoff stays intra-warp (no shuffles).
// SMEM: Qs[128][36] f32 | Ks[2][64][36] f32 | Vs[2][256 ch][72 keys] bf16
// ---------------------------------------------------------------------------
constexpr int QS_F = 0;
constexpr int KS_F = 128 * 36;                       // 4608 floats
constexpr int VS_B = (KS_F + 2 * 64 * 36) * 4;       // 36864 bytes
constexpr int VBUF_B = 256 * 72 * 2;                 // 36864 bytes
constexpr int SMEM_ATTN = VS_B + 2 * VBUF_B;         // 110592 B

__global__ void __launch_bounds__(256, 1) attn_mma_kernel(
    const float* __restrict__ x, const float* __restrict__ gamma_p,
    float* __restrict__ out)
{
    extern __shared__ __align__(16) char smc[];
    float* sm = (float*)smc;
    const int tid  = threadIdx.x;
    const int lane = tid & 31, wid = tid >> 5;
    const int b   = blockIdx.y;
    const int nt  = blockIdx.x * MROWS;
    const int m0  = wid * 16;          // distinct 16-row slab per warp
    const int g = lane >> 2, t = lane & 3;

    const float* qt = g_qt + (size_t)b * NPIX * D8;
    const float* kq = g_kt + (size_t)b * NPIX * D8;
    const __nv_bfloat16* vb = g_v + (size_t)b * C_IN * NPIX;

    const uint32_t sb = smem_u32(smc);

    // Q tile -> smem [128][36] f32
    #pragma unroll
    for (int i = tid; i < 1024; i += 256) {
        int r = i >> 3, cg = i & 7;
        *(float4*)&sm[QS_F + r * 36 + cg * 4] =
            *(const float4*)&qt[(size_t)(nt + r) * D8 + cg * 4];
    }

    // Prefetch key-tiles 0 and 1
    #pragma unroll
    for (int pb = 0; pb < 2; pb++) {
        const int mt = pb * KT;
        #pragma unroll
        for (int i = tid; i < 512; i += 256) {
            int r = i >> 3, cg = i & 7;
            cp16(sb + (uint32_t)(KS_F + pb * 2304 + r * 36 + cg * 4) * 4,
                 kq + (size_t)(mt + r) * D8 + cg * 4);
        }
        #pragma unroll
        for (int i = tid; i < 2048; i += 256) {
            int c = i >> 3, m4 = i & 7;
            cp16(sb + (uint32_t)(VS_B + pb * VBUF_B + c * 144 + m4 * 16),
                 vb + (size_t)c * NPIX + mt + m4 * 8);
        }
        CP_COMMIT();
    }

    float o[32][4];
    #pragma unroll
    for (int j = 0; j < 32; j++)
        #pragma unroll
        for (int k = 0; k < 4; k++) o[j][k] = 0.f;

    float lsum[2] = {0.f, 0.f};

    #pragma unroll 1
    for (int tt = 0; tt < NTILES; tt++) {
        const int buf = tt & 1;
        if (tt < NTILES - 1) { CP_WAIT1(); } else { CP_WAIT0(); }
        __syncthreads();

        const float* Ks = sm + KS_F + buf * 2304;
        const uint32_t* V32 = (const uint32_t*)(smc + VS_B + buf * VBUF_B);

        // ---- QK (tf32): S[16 rows][64 keys] per warp ----
        float s[8][4];
        #pragma unroll
        for (int j = 0; j < 8; j++)
            #pragma unroll
            for (int k = 0; k < 4; k++) s[j][k] = 0.f;

        #pragma unroll
        for (int sk = 0; sk < 4; sk++) {
            const int dd = sk * 8 + t;
            float a0[4];
            a0[0] = sm[QS_F + (m0 + g) * 36 + dd];
            a0[1] = sm[QS_F + (m0 + g + 8) * 36 + dd];
            a0[2] = sm[QS_F + (m0 + g) * 36 + dd + 4];
            a0[3] = sm[QS_F + (m0 + g + 8) * 36 + dd + 4];
            #pragma unroll
            for (int n8 = 0; n8 < 8; n8++) {
                float bb[2];
                bb[0] = Ks[(n8 * 8 + g) * 36 + dd];
                bb[1] = Ks[(n8 * 8 + g) * 36 + dd + 4];
                mma16n8k8(s[n8], a0, bb);
            }
        }

        // ---- exp + pack: C-frags -> bf16 A-frags (no shuffles) ----
        uint32_t pa[4][4];
        #pragma unroll
        for (int n8 = 0; n8 < 8; n8++) {
            float p0 = __expf(s[n8][0]);
            float p1 = __expf(s[n8][1]);
            float p2 = __expf(s[n8][2]);
            float p3 = __expf(s[n8][3]);
            lsum[0] += p0 + p1;
            lsum[1] += p2 + p3;
            pa[n8 >> 1][(n8 & 1) * 2 + 0] = bf2(p0, p1);
            pa[n8 >> 1][(n8 & 1) * 2 + 1] = bf2(p2, p3);
        }

        // ---- AV (bf16): O[16 rows][256 ch] += P V^T ----
        #pragma unroll
        for (int k8 = 0; k8 < 4; k8++) {
            #pragma unroll
            for (int n8 = 0; n8 < 32; n8++) {
                const int c = n8 * 8 + g;
                uint32_t b0 = V32[c * 36 + k8 * 8 + t];
                uint32_t b1 = V32[c * 36 + k8 * 8 + t + 4];
                mma_bf16(o[n8], pa[k8], b0, b1);
            }
        }

        __syncthreads();   // all warps done reading buf before refilling it

        if (tt + 2 < NTILES) {
            const int mt = (tt + 2) * KT;
            #pragma unroll
            for (int i = tid; i < 512; i += 256) {
                int r = i >> 3, cg = i & 7;
                cp16(sb + (uint32_t)(KS_F + buf * 2304 + r * 36 + cg * 4) * 4,
                     kq + (size_t)(mt + r) * D8 + cg * 4);
            }
            #pragma unroll
            for (int i = tid; i < 2048; i += 256) {
                int c = i >> 3, m4 = i & 7;
                cp16(sb + (uint32_t)(VS_B + buf * VBUF_B + c * 144 + m4 * 16),
                     vb + (size_t)c * NPIX + mt + m4 * 8);
            }
            CP_COMMIT();
        }
    }

    // ---- epilogue: out = gamma * O / l + x ----
    #pragma unroll
    for (int h = 0; h < 2; h++) {
        lsum[h] += __shfl_xor_sync(0xffffffffu, lsum[h], 1);
        lsum[h] += __shfl_xor_sync(0xffffffffu, lsum[h], 2);
    }
    const float gma = gamma_p[0];
    const float inv0 = gma / lsum[0];
    const float inv1 = gma / lsum[1];

    const int rbase = nt + m0 + g;
    #pragma unroll
    for (int n8 = 0; n8 < 32; n8++) {
        const int c0 = n8 * 8 + 2 * t;
        size_t gi = ((size_t)b * C_IN + c0) * NPIX + rbase;
        out[gi]            = o[n8][0] * inv0 + x[gi];
        out[gi + NPIX]     = o[n8][1] * inv0 + x[gi + NPIX];
        out[gi + 8]        = o[n8][2] * inv1 + x[gi + 8];
        out[gi + NPIX + 8] = o[n8][3] * inv1 + x[gi + NPIX + 8];
    }
}

// ---------------------------------------------------------------------------
extern "C" void kernel_launch(void* const* d_in, const int* in_sizes, int n_in,
                              void* d_out, int out_size)
{
    const float* x     = (const float*)d_in[0];
    const float* Wq    = (const float*)d_in[1];
    const float* bq    = (const float*)d_in[2];
    const float* Wk    = (const float*)d_in[3];
    const float* bk    = (const float*)d_in[4];
    const float* Wv    = (const float*)d_in[5];
    const float* bv    = (const float*)d_in[6];
    const float* gamma = (const float*)d_in[7];
    float* out = (float*)d_out;

    static bool attr_set = false;
    if (!attr_set) {
        cudaFuncSetAttribute(proj_fused,
                             cudaFuncAttributeMaxDynamicSharedMemorySize, F_SMEM);
        cudaFuncSetAttribute(attn_mma_kernel,
                             cudaFuncAttributeMaxDynamicSharedMemorySize, SMEM_ATTN);
        attr_set = true;
    }

    proj_fused<<<dim3(NPIX / 128, 1, BATCH), 512, F_SMEM>>>(
        x, Wq, bq, Wk, bk, Wv, bv);
    attn_mma_kernel<<<dim3(NPIX / MROWS, BATCH), 256, SMEM_ATTN>>>(x, gamma, out);
}

// round 16
// speedup vs baseline: 1.0060x; 1.0060x over previous
#include <cuda_runtime.h>
#include <cuda_bf16.h>
#include <cstdint>
#include <cstddef>

#define BATCH 32
#define C_IN  256
#define NPIX  1024
#define D8    32
#define KT    64
#define NTILES 16
#define MROWS 128

// Scratch (device globals: allocation-free)
__device__ float g_qt[BATCH * NPIX * D8];            // [b][n][32]  q (tf32)
__device__ float g_kt[BATCH * NPIX * D8];            // [b][n][32]  k (tf32)
__device__ __nv_bfloat16 g_v[BATCH * C_IN * NPIX];   // [b][c][n]   v (bf16)

// ---------------------------------------------------------------------------
// helpers
// ---------------------------------------------------------------------------
__device__ __forceinline__ float to_tf32(float f) {
    uint32_t u;
    asm("cvt.rna.tf32.f32 %0, %1;" : "=r"(u) : "f"(f));
    return __uint_as_float(u);
}
__device__ __forceinline__ uint32_t bf2(float lo, float hi) {
    uint32_t r;
    asm("cvt.rn.bf16x2.f32 %0, %1, %2;" : "=r"(r) : "f"(hi), "f"(lo));
    return r;
}
__device__ __forceinline__ uint32_t smem_u32(const void* p) {
    uint32_t a;
    asm("{ .reg .u64 t; cvta.to.shared.u64 t, %1; cvt.u32.u64 %0, t; }"
        : "=r"(a) : "l"(p));
    return a;
}
__device__ __forceinline__ void mma16n8k8(float* d, const float* a, const float* b) {
    asm volatile("mma.sync.aligned.m16n8k8.row.col.f32.tf32.tf32.f32 "
        "{%0,%1,%2,%3}, {%4,%5,%6,%7}, {%8,%9}, {%0,%1,%2,%3};"
        : "+f"(d[0]), "+f"(d[1]), "+f"(d[2]), "+f"(d[3])
        : "r"(__float_as_uint(a[0])), "r"(__float_as_uint(a[1])),
          "r"(__float_as_uint(a[2])), "r"(__float_as_uint(a[3])),
          "r"(__float_as_uint(b[0])), "r"(__float_as_uint(b[1])));
}
__device__ __forceinline__ void mma_bf16(float* d, const uint32_t* a,
                                         uint32_t b0, uint32_t b1) {
    asm volatile("mma.sync.aligned.m16n8k16.row.col.f32.bf16.bf16.f32 "
        "{%0,%1,%2,%3}, {%4,%5,%6,%7}, {%8,%9}, {%0,%1,%2,%3};"
        : "+f"(d[0]), "+f"(d[1]), "+f"(d[2]), "+f"(d[3])
        : "r"(a[0]), "r"(a[1]), "r"(a[2]), "r"(a[3]), "r"(b0), "r"(b1));
}
__device__ __forceinline__ void ldsm_x4(uint32_t& r0, uint32_t& r1,
                                        uint32_t& r2, uint32_t& r3, uint32_t addr) {
    asm volatile("ldmatrix.sync.aligned.m8n8.x4.shared.b16 {%0,%1,%2,%3}, [%4];"
        : "=r"(r0), "=r"(r1), "=r"(r2), "=r"(r3) : "r"(addr));
}
__device__ __forceinline__ void cp16(uint32_t dst, const void* src) {
    asm volatile("cp.async.cg.shared.global [%0], [%1], 16;" :: "r"(dst), "l"(src));
}
#define CP_COMMIT() asm volatile("cp.async.commit_group;" ::: "memory")
#define CP_WAIT1()  asm volatile("cp.async.wait_group 1;" ::: "memory")
#define CP_WAIT0()  asm volatile("cp.async.wait_group 0;" ::: "memory")

// ---------------------------------------------------------------------------
// FUSED projection kernel: q, k, v in one pass over x (R14, unchanged).
// ---------------------------------------------------------------------------
constexpr int PX_STRIDE = 136;
constexpr int PX_BUF    = 32 * PX_STRIDE;            // 4352 floats
constexpr int F_WS      = 2 * PX_BUF;                // 8704
constexpr int F_WBUF    = 320 * 36;                  // 11520
constexpr int F_SMEM    = (2 * PX_BUF + 2 * F_WBUF) * 4;   // 126976 B

__global__ void __launch_bounds__(512, 1) proj_fused(
    const float* __restrict__ x,
    const float* __restrict__ Wq, const float* __restrict__ bq,
    const float* __restrict__ Wk, const float* __restrict__ bk,
    const float* __restrict__ Wv, const float* __restrict__ bv)
{
    extern __shared__ float sm[];
    const int tid = threadIdx.x, lane = tid & 31, wid = tid >> 5;
    const int b = blockIdx.z, n0 = blockIdx.x * 128;
    const int m0  = (wid >> 2) * 32;     // 32-px slab
    const int ch0 = (wid & 3) * 80;      // 80-ch slab
    const int g = lane >> 2, t = lane & 3;
    const uint32_t sb = smem_u32(sm);
    const float* xb = x + (size_t)b * C_IN * NPIX;

    #pragma unroll
    for (int pb = 0; pb < 2; pb++) {
        const int kt = pb * 32;
        #pragma unroll
        for (int i = tid; i < 1024; i += 512) {
            int r = i >> 5, cg = i & 31;
            cp16(sb + (uint32_t)(pb * PX_BUF + r * PX_STRIDE + cg * 4) * 4,
                 xb + (size_t)(kt + r) * NPIX + n0 + cg * 4);
        }
        #pragma unroll
        for (int i = tid; i < 2560; i += 512) {
            int r = i >> 3, cg = i & 7;
            const float* src = (r < 32)  ? Wq + (size_t)r * C_IN + kt + cg * 4
                             : (r < 64)  ? Wk + (size_t)(r - 32) * C_IN + kt + cg * 4
                                         : Wv + (size_t)(r - 64) * C_IN + kt + cg * 4;
            cp16(sb + (uint32_t)(F_WS + pb * F_WBUF + r * 36 + cg * 4) * 4, src);
        }
        CP_COMMIT();
    }

    float acc[2][10][4] = {};

    #pragma unroll 1
    for (int j = 0; j < 8; j++) {
        if (j < 7) { CP_WAIT1(); } else { CP_WAIT0(); }
        __syncthreads();
        const int buf = j & 1;
        const float* xs = sm + buf * PX_BUF;
        const float* ws = sm + F_WS + buf * F_WBUF + ch0 * 36;

        #pragma unroll
        for (int k8 = 0; k8 < 4; k8++) {
            const int k = k8 * 8 + t;
            float a0[4], a1[4];
            a0[0] = xs[k * PX_STRIDE + m0 + g];
            a0[1] = xs[k * PX_STRIDE + m0 + g + 8];
            a0[2] = xs[(k + 4) * PX_STRIDE + m0 + g];
            a0[3] = xs[(k + 4) * PX_STRIDE + m0 + g + 8];
            a1[0] = xs[k * PX_STRIDE + m0 + g + 16];
            a1[1] = xs[k * PX_STRIDE + m0 + g + 24];
            a1[2] = xs[(k + 4) * PX_STRIDE + m0 + g + 16];
            a1[3] = xs[(k + 4) * PX_STRIDE + m0 + g + 24];
            #pragma unroll
            for (int n8 = 0; n8 < 10; n8++) {
                float bb[2];
                bb[0] = ws[(n8 * 8 + g) * 36 + k];
                bb[1] = ws[(n8 * 8 + g) * 36 + k + 4];
                mma16n8k8(acc[0][n8], a0, bb);
                mma16n8k8(acc[1][n8], a1, bb);
            }
        }
        __syncthreads();

        if (j + 2 < 8) {
            const int kt = (j + 2) * 32;
            #pragma unroll
            for (int i = tid; i < 1024; i += 512) {
                int r = i >> 5, cg = i & 31;
                cp16(sb + (uint32_t)(buf * PX_BUF + r * PX_STRIDE + cg * 4) * 4,
                     xb + (size_t)(kt + r) * NPIX + n0 + cg * 4);
            }
            #pragma unroll
            for (int i = tid; i < 2560; i += 512) {
                int r = i >> 3, cg = i & 7;
                const float* src = (r < 32)  ? Wq + (size_t)r * C_IN + kt + cg * 4
                                 : (r < 64)  ? Wk + (size_t)(r - 32) * C_IN + kt + cg * 4
                                             : Wv + (size_t)(r - 64) * C_IN + kt + cg * 4;
                cp16(sb + (uint32_t)(F_WS + buf * F_WBUF + r * 36 + cg * 4) * 4, src);
            }
            CP_COMMIT();
        }
    }

    // ---- epilogue: scatter q / k, transpose v ----
    __nv_bfloat16* Ts = (__nv_bfloat16*)sm;   // [256 vch][136 px], reuses buffers
    #pragma unroll
    for (int mt2 = 0; mt2 < 2; mt2++) {
        const int row = m0 + mt2 * 16 + g;    // local pixel 0..127
        #pragma unroll
        for (int n8 = 0; n8 < 10; n8++) {
            const int ch = ch0 + n8 * 8 + 2 * t;
            if (ch < 32) {               // ---- q ----
                float b0 = bq[ch], b1 = bq[ch + 1];
                float2 lo = make_float2(to_tf32(acc[mt2][n8][0] + b0),
                                        to_tf32(acc[mt2][n8][1] + b1));
                float2 hi = make_float2(to_tf32(acc[mt2][n8][2] + b0),
                                        to_tf32(acc[mt2][n8][3] + b1));
                *(float2*)&g_qt[((size_t)b * NPIX + n0 + row) * D8 + ch] = lo;
                *(float2*)&g_qt[((size_t)b * NPIX + n0 + row + 8) * D8 + ch] = hi;
            } else if (ch < 64) {        // ---- k ----
                const int col = ch - 32;
                float b0 = bk[col], b1 = bk[col + 1];
                float2 lo = make_float2(to_tf32(acc[mt2][n8][0] + b0),
                                        to_tf32(acc[mt2][n8][1] + b1));
                float2 hi = make_float2(to_tf32(acc[mt2][n8][2] + b0),
                                        to_tf32(acc[mt2][n8][3] + b1));
                *(float2*)&g_kt[((size_t)b * NPIX + n0 + row) * D8 + col] = lo;
                *(float2*)&g_kt[((size_t)b * NPIX + n0 + row + 8) * D8 + col] = hi;
            } else {                     // ---- v -> SMEM transpose ----
                const int vc = ch - 64;
                float b0 = bv[vc], b1 = bv[vc + 1];
                Ts[vc * 136 + row]           = __float2bfloat16(acc[mt2][n8][0] + b0);
                Ts[(vc + 1) * 136 + row]     = __float2bfloat16(acc[mt2][n8][1] + b1);
                Ts[vc * 136 + row + 8]       = __float2bfloat16(acc[mt2][n8][2] + b0);
                Ts[(vc + 1) * 136 + row + 8] = __float2bfloat16(acc[mt2][n8][3] + b1);
            }
        }
    }
    __syncthreads();
    #pragma unroll
    for (int i = tid; i < 256 * 64; i += 512) {
        int c = i >> 6, w = i & 63;
        ((uint32_t*)&g_v[((size_t)b * C_IN + c) * NPIX + n0])[w] =
            ((const uint32_t*)&Ts[c * 136])[w];
    }
}

// ---------------------------------------------------------------------------
// Flash attention: QK tf32 mma, AV bf16 mma.  MROWS = 128.
// Warp wid owns rows [wid*16, wid*16+16) and ALL 256 channels (R13 map).
// R15: triple-buffered K/V with ONE __syncthreads per tile; AV B-frags via
// ldmatrix.x4 (one LDSM feeds two mmas; 256 LDS -> 64 LDSM per thread/tile).
// SMEM: Qs[128][36] f32 | Ks[3][64][36] f32 | Vs[3][256 ch][72 keys] bf16
// ---------------------------------------------------------------------------
constexpr int QS_F   = 0;
constexpr int KS_F   = 128 * 36;                     // 4608 floats
constexpr int KBUF_F = 64 * 36;                      // 2304 floats
constexpr int VS_B   = (KS_F + 3 * KBUF_F) * 4;      // 46080 bytes
constexpr int VBUF_B = 256 * 72 * 2;                 // 36864 bytes
constexpr int SMEM_ATTN = VS_B + 3 * VBUF_B;         // 156672 B

__global__ void __launch_bounds__(256, 1) attn_mma_kernel(
    const float* __restrict__ x, const float* __restrict__ gamma_p,
    float* __restrict__ out)
{
    extern __shared__ __align__(16) char smc[];
    float* sm = (float*)smc;
    const int tid  = threadIdx.x;
    const int lane = tid & 31, wid = tid >> 5;
    const int b   = blockIdx.y;
    const int nt  = blockIdx.x * MROWS;
    const int m0  = wid * 16;          // distinct 16-row slab per warp
    const int g = lane >> 2, t = lane & 3;

    const float* qt = g_qt + (size_t)b * NPIX * D8;
    const float* kq = g_kt + (size_t)b * NPIX * D8;
    const __nv_bfloat16* vb = g_v + (size_t)b * C_IN * NPIX;

    const uint32_t sb = smem_u32(smc);

    // ldmatrix per-thread address components (see mapping proof in theory):
    //   mat = lane>>3; row-within-pair = ((lane>>4)<<3) + (lane&7);
    //   key offset = ((lane>>3)&1)*8
    const int r_l   = ((lane >> 4) << 3) + (lane & 7);
    const int k_off = ((lane >> 3) & 1) << 3;
    const uint32_t ldsm_base = (uint32_t)(r_l * 144 + k_off * 2);

    // Q tile -> smem [128][36] f32
    #pragma unroll
    for (int i = tid; i < 1024; i += 256) {
        int r = i >> 3, cg = i & 7;
        *(float4*)&sm[QS_F + r * 36 + cg * 4] =
            *(const float4*)&qt[(size_t)(nt + r) * D8 + cg * 4];
    }

    // Prefetch key-tiles 0 and 1 into bufs 0,1
    #pragma unroll
    for (int pb = 0; pb < 2; pb++) {
        const int mt = pb * KT;
        #pragma unroll
        for (int i = tid; i < 512; i += 256) {
            int r = i >> 3, cg = i & 7;
            cp16(sb + (uint32_t)(KS_F + pb * KBUF_F + r * 36 + cg * 4) * 4,
                 kq + (size_t)(mt + r) * D8 + cg * 4);
        }
        #pragma unroll
        for (int i = tid; i < 2048; i += 256) {
            int c = i >> 3, m4 = i & 7;
            cp16(sb + (uint32_t)(VS_B + pb * VBUF_B + c * 144 + m4 * 16),
                 vb + (size_t)c * NPIX + mt + m4 * 8);
        }
        CP_COMMIT();
    }

    float o[32][4];
    #pragma unroll
    for (int j = 0; j < 32; j++)
        #pragma unroll
        for (int k = 0; k < 4; k++) o[j][k] = 0.f;

    float lsum[2] = {0.f, 0.f};

    #pragma unroll 1
    for (int tt = 0; tt < NTILES; tt++) {
        const int buf = tt % 3;
        if (tt < NTILES - 1) { CP_WAIT1(); } else { CP_WAIT0(); }
        __syncthreads();   // single barrier: tile tt ready AND all warps past tt-1

        // Refill buf (tt+2)%3 (last read at tile tt-1, fenced by the barrier)
        if (tt + 2 < NTILES) {
            const int nbuf = (tt + 2) % 3;
            const int mt = (tt + 2) * KT;
            #pragma unroll
            for (int i = tid; i < 512; i += 256) {
                int r = i >> 3, cg = i & 7;
                cp16(sb + (uint32_t)(KS_F + nbuf * KBUF_F + r * 36 + cg * 4) * 4,
                     kq + (size_t)(mt + r) * D8 + cg * 4);
            }
            #pragma unroll
            for (int i = tid; i < 2048; i += 256) {
                int c = i >> 3, m4 = i & 7;
                cp16(sb + (uint32_t)(VS_B + nbuf * VBUF_B + c * 144 + m4 * 16),
                     vb + (size_t)c * NPIX + mt + m4 * 8);
            }
            CP_COMMIT();
        }

        const float* Ks = sm + KS_F + buf * KBUF_F;
        const uint32_t vbase = sb + VS_B + buf * VBUF_B + ldsm_base;

        // ---- QK (tf32): S[16 rows][64 keys] per warp ----
        float s[8][4];
        #pragma unroll
        for (int j = 0; j < 8; j++)
            #pragma unroll
            for (int k = 0; k < 4; k++) s[j][k] = 0.f;

        #pragma unroll
        for (int sk = 0; sk < 4; sk++) {
            const int dd = sk * 8 + t;
            float a0[4];
            a0[0] = sm[QS_F + (m0 + g) * 36 + dd];
            a0[1] = sm[QS_F + (m0 + g + 8) * 36 + dd];
            a0[2] = sm[QS_F + (m0 + g) * 36 + dd + 4];
            a0[3] = sm[QS_F + (m0 + g + 8) * 36 + dd + 4];
            #pragma unroll
            for (int n8 = 0; n8 < 8; n8++) {
                float bb[2];
                bb[0] = Ks[(n8 * 8 + g) * 36 + dd];
                bb[1] = Ks[(n8 * 8 + g) * 36 + dd + 4];
                mma16n8k8(s[n8], a0, bb);
            }
        }

        // ---- exp + pack: C-frags -> bf16 A-frags (no shuffles) ----
        uint32_t pa[4][4];
        #pragma unroll
        for (int n8 = 0; n8 < 8; n8++) {
            float p0 = __expf(s[n8][0]);
            float p1 = __expf(s[n8][1]);
            float p2 = __expf(s[n8][2]);
            float p3 = __expf(s[n8][3]);
            lsum[0] += p0 + p1;
            lsum[1] += p2 + p3;
            pa[n8 >> 1][(n8 & 1) * 2 + 0] = bf2(p0, p1);
            pa[n8 >> 1][(n8 & 1) * 2 + 1] = bf2(p2, p3);
        }

        // ---- AV (bf16): O[16 rows][256 ch] += P V^T, B via ldmatrix.x4 ----
        #pragma unroll
        for (int k8 = 0; k8 < 4; k8++) {
            #pragma unroll
            for (int np = 0; np < 16; np++) {
                uint32_t r0, r1, r2, r3;
                ldsm_x4(r0, r1, r2, r3, vbase + np * 2304 + k8 * 32);
                mma_bf16(o[np * 2],     pa[k8], r0, r1);
                mma_bf16(o[np * 2 + 1], pa[k8], r2, r3);
            }
        }
    }

    // ---- epilogue: out = gamma * O / l + x ----
    #pragma unroll
    for (int h = 0; h < 2; h++) {
        lsum[h] += __shfl_xor_sync(0xffffffffu, lsum[h], 1);
        lsum[h] += __shfl_xor_sync(0xffffffffu, lsum[h], 2);
    }
    const float gma = gamma_p[0];
    const float inv0 = gma / lsum[0];
    const float inv1 = gma / lsum[1];

    const int rbase = nt + m0 + g;
    #pragma unroll
    for (int n8 = 0; n8 < 32; n8++) {
        const int c0 = n8 * 8 + 2 * t;
        size_t gi = ((size_t)b * C_IN + c0) * NPIX + rbase;
        out[gi]            = o[n8][0] * inv0 + x[gi];
        out[gi + NPIX]     = o[n8][1] * inv0 + x[gi + NPIX];
        out[gi + 8]        = o[n8][2] * inv1 + x[gi + 8];
        out[gi + NPIX + 8] = o[n8][3] * inv1 + x[gi + NPIX + 8];
    }
}

// ---------------------------------------------------------------------------
extern "C" void kernel_launch(void* const* d_in, const int* in_sizes, int n_in,
                              void* d_out, int out_size)
{
    const float* x     = (const float*)d_in[0];
    const float* Wq    = (const float*)d_in[1];
    const float* bq    = (const float*)d_in[2];
    const float* Wk    = (const float*)d_in[3];
    const float* bk    = (const float*)d_in[4];
    const float* Wv    = (const float*)d_in[5];
    const float* bv    = (const float*)d_in[6];
    const float* gamma = (const float*)d_in[7];
    float* out = (float*)d_out;

    static bool attr_set = false;
    if (!attr_set) {
        cudaFuncSetAttribute(proj_fused,
                             cudaFuncAttributeMaxDynamicSharedMemorySize, F_SMEM);
        cudaFuncSetAttribute(attn_mma_kernel,
                             cudaFuncAttributeMaxDynamicSharedMemorySize, SMEM_ATTN);
        attr_set = true;
    }

    proj_fused<<<dim3(NPIX / 128, 1, BATCH), 512, F_SMEM>>>(
        x, Wq, bq, Wk, bk, Wv, bv);
    attn_mma_kernel<<<dim3(NPIX / MROWS, BATCH), 256, SMEM_ATTN>>>(x, gamma, out);
}